// round 1
// baseline (speedup 1.0000x reference)
#include <cuda_runtime.h>
#include <cuda_bf16.h>
#include <math.h>

// Problem shape (fixed): B=4, S=2048, D=1024
#define BATCH 4
#define SEQ   2048
#define DIM   1024
#define ROWS  (BATCH*SEQ)          // 8192
#define QK_SCALE 0.0220970869f     // 1/sqrt(2048)

// ---------------- scratch (device globals; no allocation allowed) -----------
__device__ float g_ln1 [ROWS*DIM];
__device__ float g_q   [ROWS*DIM];
__device__ float g_k   [ROWS*DIM];
__device__ float g_v   [ROWS*DIM];
__device__ float g_ctx [ROWS*DIM];
__device__ float g_h   [ROWS*DIM];
__device__ float g_ln2 [ROWS*DIM];
__device__ float g_mlp1[ROWS*DIM];
__device__ float g_sc  [BATCH*SEQ*SEQ];   // attention scores / probs (64 MB)

// ---------------- LayerNorm (torch semantics: ddof=1, eps on std) -----------
__global__ void ln_kernel(const float* __restrict__ x,
                          const float* __restrict__ g,
                          const float* __restrict__ be,
                          float* __restrict__ y)
{
    int row = blockIdx.x;
    const float* xr = x + (size_t)row * DIM;
    int t = threadIdx.x;
    __shared__ float red[256];

    float v[4];
    float s = 0.f;
#pragma unroll
    for (int i = 0; i < 4; i++) { v[i] = xr[t + 256*i]; s += v[i]; }
    red[t] = s; __syncthreads();
    for (int st = 128; st > 0; st >>= 1) {
        if (t < st) red[t] += red[t + st];
        __syncthreads();
    }
    float mean = red[0] * (1.0f / DIM);
    __syncthreads();

    float qv = 0.f;
#pragma unroll
    for (int i = 0; i < 4; i++) { float d = v[i] - mean; qv += d * d; }
    red[t] = qv; __syncthreads();
    for (int st = 128; st > 0; st >>= 1) {
        if (t < st) red[t] += red[t + st];
        __syncthreads();
    }
    float stdv = sqrtf(red[0] / (float)(DIM - 1));
    float inv  = 1.0f / (stdv + 1e-6f);

    float* yr = y + (size_t)row * DIM;
#pragma unroll
    for (int i = 0; i < 4; i++) {
        int idx = t + 256*i;
        yr[idx] = g[idx] * (v[i] - mean) * inv + be[idx];
    }
}

// ---------------- generic NN SGEMM: C = A@B (+bias)(+res)(ReLU) -------------
// 128x128 block tile, BK=8, 256 threads, 8x8 per-thread microtile.
template<bool RELU>
__global__ void __launch_bounds__(256)
sgemm_nn(const float* __restrict__ A, const float* __restrict__ B,
         const float* __restrict__ bias, const float* __restrict__ res,
         float* __restrict__ C, int M, int N, int K,
         size_t sA, size_t sB, size_t sC)
{
    A += blockIdx.z * sA;
    B += blockIdx.z * sB;
    C += blockIdx.z * sC;
    if (res) res += blockIdx.z * sC;

    __shared__ float As[8][128];
    __shared__ float Bs[8][128];

    int tid = threadIdx.x;
    int cRow = blockIdx.y * 128;
    int cCol = blockIdx.x * 128;

    int irA = tid >> 1;            // 0..127
    int icA = (tid & 1) * 4;       // 0 or 4
    int irB = tid >> 5;            // 0..7
    int icB = (tid & 31) * 4;      // 0..124

    int ty = tid >> 4;             // 0..15
    int tx = tid & 15;             // 0..15

    float acc[8][8];
#pragma unroll
    for (int i = 0; i < 8; i++)
#pragma unroll
        for (int j = 0; j < 8; j++) acc[i][j] = 0.f;

    for (int kt = 0; kt < K; kt += 8) {
        float4 a4 = *(const float4*)(A + (size_t)(cRow + irA) * K + kt + icA);
        As[icA + 0][irA] = a4.x;
        As[icA + 1][irA] = a4.y;
        As[icA + 2][irA] = a4.z;
        As[icA + 3][irA] = a4.w;
        float4 b4 = *(const float4*)(B + (size_t)(kt + irB) * N + cCol + icB);
        *(float4*)&Bs[irB][icB] = b4;
        __syncthreads();

#pragma unroll
        for (int kk = 0; kk < 8; kk++) {
            float rm[8], rn[8];
#pragma unroll
            for (int i = 0; i < 8; i++) rm[i] = As[kk][ty * 8 + i];
#pragma unroll
            for (int j = 0; j < 8; j++) rn[j] = Bs[kk][tx * 8 + j];
#pragma unroll
            for (int i = 0; i < 8; i++)
#pragma unroll
                for (int j = 0; j < 8; j++) acc[i][j] += rm[i] * rn[j];
        }
        __syncthreads();
    }

#pragma unroll
    for (int i = 0; i < 8; i++) {
        int r = cRow + ty * 8 + i;
#pragma unroll
        for (int j0 = 0; j0 < 8; j0 += 4) {
            int c = cCol + tx * 8 + j0;
            float4 v = make_float4(acc[i][j0], acc[i][j0+1], acc[i][j0+2], acc[i][j0+3]);
            if (bias) {
                v.x += bias[c];   v.y += bias[c+1];
                v.z += bias[c+2]; v.w += bias[c+3];
            }
            if (res) {
                float4 rr = *(const float4*)(res + (size_t)r * N + c);
                v.x += rr.x; v.y += rr.y; v.z += rr.z; v.w += rr.w;
            }
            if (RELU) {
                v.x = fmaxf(v.x, 0.f); v.y = fmaxf(v.y, 0.f);
                v.z = fmaxf(v.z, 0.f); v.w = fmaxf(v.w, 0.f);
            }
            *(float4*)(C + (size_t)r * N + c) = v;
        }
    }
}

// ---------------- QK^T (NT), scaled, causal block-skip -----------------------
__global__ void __launch_bounds__(256)
qk_nt(const float* __restrict__ Q, const float* __restrict__ Km,
      float* __restrict__ Sc)
{
    int b = blockIdx.z;
    int cRow = blockIdx.y * 128;
    int cCol = blockIdx.x * 128;
    if (cCol > cRow + 127) return;   // entirely above diagonal — never read

    const float* A = Q  + (size_t)b * SEQ * DIM;
    const float* B = Km + (size_t)b * SEQ * DIM;
    float* C       = Sc + (size_t)b * SEQ * SEQ;

    __shared__ float As[8][128];
    __shared__ float Bs[8][128];

    int tid = threadIdx.x;
    int ir = tid >> 1;
    int ic = (tid & 1) * 4;
    int ty = tid >> 4;
    int tx = tid & 15;

    float acc[8][8];
#pragma unroll
    for (int i = 0; i < 8; i++)
#pragma unroll
        for (int j = 0; j < 8; j++) acc[i][j] = 0.f;

    for (int kt = 0; kt < DIM; kt += 8) {
        float4 a4 = *(const float4*)(A + (size_t)(cRow + ir) * DIM + kt + ic);
        As[ic + 0][ir] = a4.x; As[ic + 1][ir] = a4.y;
        As[ic + 2][ir] = a4.z; As[ic + 3][ir] = a4.w;
        // B tile: rows are key indices (n), contiguous in k
        float4 b4 = *(const float4*)(B + (size_t)(cCol + ir) * DIM + kt + ic);
        Bs[ic + 0][ir] = b4.x; Bs[ic + 1][ir] = b4.y;
        Bs[ic + 2][ir] = b4.z; Bs[ic + 3][ir] = b4.w;
        __syncthreads();

#pragma unroll
        for (int kk = 0; kk < 8; kk++) {
            float rm[8], rn[8];
#pragma unroll
            for (int i = 0; i < 8; i++) rm[i] = As[kk][ty * 8 + i];
#pragma unroll
            for (int j = 0; j < 8; j++) rn[j] = Bs[kk][tx * 8 + j];
#pragma unroll
            for (int i = 0; i < 8; i++)
#pragma unroll
                for (int j = 0; j < 8; j++) acc[i][j] += rm[i] * rn[j];
        }
        __syncthreads();
    }

#pragma unroll
    for (int i = 0; i < 8; i++) {
        int r = cRow + ty * 8 + i;
#pragma unroll
        for (int j0 = 0; j0 < 8; j0 += 4) {
            int c = cCol + tx * 8 + j0;
            float4 v = make_float4(acc[i][j0]   * QK_SCALE,
                                   acc[i][j0+1] * QK_SCALE,
                                   acc[i][j0+2] * QK_SCALE,
                                   acc[i][j0+3] * QK_SCALE);
            *(float4*)(C + (size_t)r * SEQ + c) = v;
        }
    }
}

// ---------------- causal softmax over one row --------------------------------
__global__ void softmax_kernel(float* __restrict__ scores)
{
    int row = blockIdx.x;             // 0..BATCH*SEQ-1
    int b = row >> 11;                // /2048
    int s = row & (SEQ - 1);
    float* p = scores + (size_t)b * SEQ * SEQ + (size_t)s * SEQ;
    int cnt = s + 1;
    int t = threadIdx.x;
    __shared__ float red[256];

    float mx = -INFINITY;
    for (int j = t; j < cnt; j += 256) mx = fmaxf(mx, p[j]);
    red[t] = mx; __syncthreads();
    for (int st = 128; st > 0; st >>= 1) {
        if (t < st) red[t] = fmaxf(red[t], red[t + st]);
        __syncthreads();
    }
    mx = red[0]; __syncthreads();

    float sum = 0.f;
    for (int j = t; j < cnt; j += 256) {
        float e = __expf(p[j] - mx);
        p[j] = e;
        sum += e;
    }
    red[t] = sum; __syncthreads();
    for (int st = 128; st > 0; st >>= 1) {
        if (t < st) red[t] += red[t + st];
        __syncthreads();
    }
    float inv = 1.0f / red[0];

    for (int j = t; j < cnt; j += 256) p[j] *= inv;
    for (int j = cnt + t; j < SEQ; j += 256) p[j] = 0.f;  // exact zeros for AV
}

// ---------------- launch -----------------------------------------------------
extern "C" void kernel_launch(void* const* d_in, const int* in_sizes, int n_in,
                              void* d_out, int out_size)
{
    const float* x   = (const float*)d_in[0];
    const float* wq  = (const float*)d_in[1];
    const float* bq  = (const float*)d_in[2];
    const float* wk  = (const float*)d_in[3];
    const float* bk  = (const float*)d_in[4];
    const float* wv  = (const float*)d_in[5];
    const float* bv  = (const float*)d_in[6];
    const float* wo  = (const float*)d_in[7];
    const float* bo  = (const float*)d_in[8];
    const float* w1  = (const float*)d_in[9];
    const float* b1  = (const float*)d_in[10];
    const float* w2  = (const float*)d_in[11];
    const float* b2  = (const float*)d_in[12];
    const float* g1  = (const float*)d_in[13];
    const float* be1 = (const float*)d_in[14];
    const float* g2  = (const float*)d_in[15];
    const float* be2 = (const float*)d_in[16];
    float* out = (float*)d_out;

    float *ln1, *q, *k, *v, *ctx, *h, *ln2, *mlp1, *sc;
    cudaGetSymbolAddress((void**)&ln1,  g_ln1);
    cudaGetSymbolAddress((void**)&q,    g_q);
    cudaGetSymbolAddress((void**)&k,    g_k);
    cudaGetSymbolAddress((void**)&v,    g_v);
    cudaGetSymbolAddress((void**)&ctx,  g_ctx);
    cudaGetSymbolAddress((void**)&h,    g_h);
    cudaGetSymbolAddress((void**)&ln2,  g_ln2);
    cudaGetSymbolAddress((void**)&mlp1, g_mlp1);
    cudaGetSymbolAddress((void**)&sc,   g_sc);

    dim3 blk(256);
    dim3 gemm_grid(DIM / 128, ROWS / 128, 1);      // (8, 64)
    dim3 qk_grid(SEQ / 128, SEQ / 128, BATCH);     // (16,16,4)
    dim3 av_grid(DIM / 128, SEQ / 128, BATCH);     // (8,16,4)

    // 1. LN1
    ln_kernel<<<ROWS, 256>>>(x, g1, be1, ln1);
    // 2-4. Q, K, V projections
    sgemm_nn<false><<<gemm_grid, blk>>>(ln1, wq, bq, nullptr, q,
                                        ROWS, DIM, DIM, 0, 0, 0);
    sgemm_nn<false><<<gemm_grid, blk>>>(ln1, wk, bk, nullptr, k,
                                        ROWS, DIM, DIM, 0, 0, 0);
    sgemm_nn<false><<<gemm_grid, blk>>>(ln1, wv, bv, nullptr, v,
                                        ROWS, DIM, DIM, 0, 0, 0);
    // 5. scores = Q K^T / sqrt(S)   (causal block-skip)
    qk_nt<<<qk_grid, blk>>>(q, k, sc);
    // 6. causal softmax
    softmax_kernel<<<ROWS, 256>>>(sc);
    // 7. ctx = P V  (batched NN)
    sgemm_nn<false><<<av_grid, blk>>>(sc, v, nullptr, nullptr, ctx,
                                      SEQ, DIM, SEQ,
                                      (size_t)SEQ * SEQ, (size_t)SEQ * DIM,
                                      (size_t)SEQ * DIM);
    // 8. h = ctx@wo + bo + x
    sgemm_nn<false><<<gemm_grid, blk>>>(ctx, wo, bo, x, h,
                                        ROWS, DIM, DIM, 0, 0, 0);
    // 9. LN2
    ln_kernel<<<ROWS, 256>>>(h, g2, be2, ln2);
    // 10. mlp1 = relu(ln2@w1 + b1)
    sgemm_nn<true><<<gemm_grid, blk>>>(ln2, w1, b1, nullptr, mlp1,
                                       ROWS, DIM, DIM, 0, 0, 0);
    // 11. out = mlp1@w2 + b2 + h
    sgemm_nn<false><<<gemm_grid, blk>>>(mlp1, w2, b2, h, out,
                                        ROWS, DIM, DIM, 0, 0, 0);
}

// round 4
// speedup vs baseline: 3.0422x; 3.0422x over previous
#include <cuda_runtime.h>
#include <cuda_bf16.h>
#include <stdint.h>
#include <math.h>

// Problem shape (fixed): B=4, S=2048, D=1024
#define BATCH 4
#define SEQ   2048
#define DIM   1024
#define ROWS  (BATCH*SEQ)          // 8192
#define QK_SCALE 0.0220970869f     // 1/sqrt(2048)

// GEMM tiling: CTA 128x64, K-chunk 64 fp32; 8 warps -> warp tile 32x32
#define BM 128
#define BN 64
#define BK 64

// ---------------- scratch (device globals; no allocation allowed) -----------
__device__ float g_ln1 [ROWS*DIM];
__device__ float g_q   [ROWS*DIM];
__device__ float g_k   [ROWS*DIM];
__device__ float g_v   [ROWS*DIM];
__device__ float g_ctx [ROWS*DIM];
__device__ float g_h   [ROWS*DIM];
__device__ float g_ln2 [ROWS*DIM];
__device__ float g_mlp1[ROWS*DIM];
__device__ float g_sc  [(size_t)BATCH*SEQ*SEQ];   // attention scores (64 MB)
__device__ float g_wt  [6*DIM*DIM];               // transposed weights
__device__ float g_vt  [ROWS*DIM];                // transposed V

// ======================= helpers =============================================
__device__ __forceinline__ uint32_t smem_u32(const void* p) {
    uint32_t a;
    asm("{ .reg .u64 t; cvta.to.shared.u64 t, %1; cvt.u32.u64 %0, t; }"
        : "=r"(a) : "l"(p));
    return a;
}
__device__ __forceinline__ uint32_t sw128(uint32_t o) { return o ^ ((o >> 3) & 0x70); }

// split fp32 pair -> packed bf16x2 hi + lo(residual)
__device__ __forceinline__ void bf16_split2(float x, float y,
                                            uint32_t& hi, uint32_t& lo) {
    asm("cvt.rn.bf16x2.f32 %0, %1, %2;" : "=r"(hi) : "f"(y), "f"(x));
    float hx = __uint_as_float(hi << 16);
    float hy = __uint_as_float(hi & 0xffff0000u);
    float lx = x - hx, ly = y - hy;
    asm("cvt.rn.bf16x2.f32 %0, %1, %2;" : "=r"(lo) : "f"(ly), "f"(lx));
}

__device__ __forceinline__ void ldsm_x4(uint32_t* r, uint32_t addr) {
    asm volatile("ldmatrix.sync.aligned.m8n8.x4.shared.b16 {%0,%1,%2,%3}, [%4];"
                 : "=r"(r[0]), "=r"(r[1]), "=r"(r[2]), "=r"(r[3]) : "r"(addr));
}
__device__ __forceinline__ void mma16816(float* c, const uint32_t* a,
                                         uint32_t b0, uint32_t b1) {
    asm volatile("mma.sync.aligned.m16n8k16.row.col.f32.bf16.bf16.f32 "
                 "{%0,%1,%2,%3}, {%4,%5,%6,%7}, {%8,%9}, {%0,%1,%2,%3};"
                 : "+f"(c[0]), "+f"(c[1]), "+f"(c[2]), "+f"(c[3])
                 : "r"(a[0]), "r"(a[1]), "r"(a[2]), "r"(a[3]), "r"(b0), "r"(b1));
}

// ============ HMMA bf16x3 GEMM: C[M,N] = A[M,K] @ B[N,K]^T ===================
// MODE: 0=dense (+bias,+res,RELU), 1=QK (scale, causal block-skip),
//       2=AV (causal K-limit)
template<int MODE, bool RELU>
__global__ void __launch_bounds__(256, 2)
hmma_gemm(const float* __restrict__ A, const float* __restrict__ B,
          const float* __restrict__ bias, const float* __restrict__ res,
          float* __restrict__ C, int K, int ldA, int ldB, int ldC,
          size_t sA, size_t sB, size_t sC)
{
    int cRow = blockIdx.y * BM;
    int cCol = blockIdx.x * BN;
    if (MODE == 1 && cCol > cRow + BM - 1) return;   // fully above diagonal

    A += blockIdx.z * sA;
    B += blockIdx.z * sB;
    C += blockIdx.z * sC;
    if (res) res += blockIdx.z * sC;

    int nc = (MODE == 2) ? (cRow + BM) / BK : K / BK;

    // 48KB static smem: Ahi | Alo | Bhi | Blo  (bf16, SW128 swizzled, 128B rows)
    __shared__ __align__(1024) char sm[49152];
    uint32_t aHi = smem_u32(sm);
    uint32_t aLo = aHi + 16384;
    uint32_t bHi = aHi + 32768;
    uint32_t bLo = aHi + 40960;

    int tid = threadIdx.x, lane = tid & 31, wid = tid >> 5;
    int wm = wid >> 1, wn = wid & 1;      // 4x2 warp grid, warp tile 32x32

    float acc[2][4][4];
#pragma unroll
    for (int mi = 0; mi < 2; mi++)
#pragma unroll
        for (int ni = 0; ni < 4; ni++)
#pragma unroll
            for (int j = 0; j < 4; j++) acc[mi][ni][j] = 0.f;

    // per-thread ldmatrix offsets (unswizzled byte offsets within a tile)
    int a_r  = (lane & 15);
    int a_kb = (lane >> 4) << 4;                  // 0 or 16 bytes
    int b_n  = (lane & 7) + ((lane >> 4) << 3);   // 0..15
    int b_kb = ((lane >> 3) & 1) << 4;            // 0 or 16 bytes

    for (int c = 0; c < nc; c++) {
        int kt = c * BK;
        // ---- stage: load fp32, split, store bf16 hi/lo (swizzled) ----
#pragma unroll
        for (int i = 0; i < 8; i++) {
            int fi = tid + i * 256;               // 0..2047
            int row = fi >> 4;
            int c4  = fi & 15;
            float4 av = *(const float4*)(A + (size_t)(cRow + row) * ldA + kt + c4 * 4);
            uint32_t h01, l01, h23, l23;
            bf16_split2(av.x, av.y, h01, l01);
            bf16_split2(av.z, av.w, h23, l23);
            uint64_t hv = (uint64_t)h01 | ((uint64_t)h23 << 32);
            uint64_t lv = (uint64_t)l01 | ((uint64_t)l23 << 32);
            uint32_t off = sw128((uint32_t)(row * 128 + c4 * 8));
            asm volatile("st.shared.b64 [%0], %1;" :: "r"(aHi + off), "l"(hv) : "memory");
            asm volatile("st.shared.b64 [%0], %1;" :: "r"(aLo + off), "l"(lv) : "memory");
        }
#pragma unroll
        for (int i = 0; i < 4; i++) {
            int fi = tid + i * 256;               // 0..1023
            int row = fi >> 4;                    // 0..63
            int c4  = fi & 15;
            float4 bv = *(const float4*)(B + (size_t)(cCol + row) * ldB + kt + c4 * 4);
            uint32_t h01, l01, h23, l23;
            bf16_split2(bv.x, bv.y, h01, l01);
            bf16_split2(bv.z, bv.w, h23, l23);
            uint64_t hv = (uint64_t)h01 | ((uint64_t)h23 << 32);
            uint64_t lv = (uint64_t)l01 | ((uint64_t)l23 << 32);
            uint32_t off = sw128((uint32_t)(row * 128 + c4 * 8));
            asm volatile("st.shared.b64 [%0], %1;" :: "r"(bHi + off), "l"(hv) : "memory");
            asm volatile("st.shared.b64 [%0], %1;" :: "r"(bLo + off), "l"(lv) : "memory");
        }
        __syncthreads();

        // ---- compute: 4 k-steps of 16 ----
#pragma unroll
        for (int ks = 0; ks < 4; ks++) {
            uint32_t ah[2][4], al[2][4];
#pragma unroll
            for (int mi = 0; mi < 2; mi++) {
                int r = wm * 32 + mi * 16 + a_r;
                uint32_t off = sw128((uint32_t)(r * 128 + ks * 32 + a_kb));
                ldsm_x4(ah[mi], aHi + off);
                ldsm_x4(al[mi], aLo + off);
            }
            // B fragments: storage is [n][k] (k contiguous) == col-major KxN,
            // so NON-trans ldmatrix with n-row addresses yields b0/b1 directly.
            uint32_t bh[2][4], bl[2][4];
#pragma unroll
            for (int np = 0; np < 2; np++) {
                int n = wn * 32 + np * 16 + b_n;
                uint32_t off = sw128((uint32_t)(n * 128 + ks * 32 + b_kb));
                ldsm_x4(bh[np], bHi + off);
                ldsm_x4(bl[np], bLo + off);
            }
#pragma unroll
            for (int mi = 0; mi < 2; mi++)
#pragma unroll
                for (int ni = 0; ni < 4; ni++) {
                    int np = ni >> 1, hf = (ni & 1) * 2;
                    mma16816(acc[mi][ni], ah[mi], bh[np][hf], bh[np][hf + 1]);
                    mma16816(acc[mi][ni], ah[mi], bl[np][hf], bl[np][hf + 1]);
                    mma16816(acc[mi][ni], al[mi], bh[np][hf], bh[np][hf + 1]);
                }
        }
        __syncthreads();
    }

    // ---- epilogue ----
#pragma unroll
    for (int mi = 0; mi < 2; mi++) {
#pragma unroll
        for (int ni = 0; ni < 4; ni++) {
            int row0 = cRow + wm * 32 + mi * 16 + (lane >> 2);
            int col  = cCol + wn * 32 + ni * 8 + (lane & 3) * 2;
#pragma unroll
            for (int hh = 0; hh < 2; hh++) {       // c0,c1 then c2,c3 (row+8)
                int r = row0 + hh * 8;
                float v0 = acc[mi][ni][hh * 2];
                float v1 = acc[mi][ni][hh * 2 + 1];
                if (MODE == 1) { v0 *= QK_SCALE; v1 *= QK_SCALE; }
                if (MODE == 0 && bias) { v0 += bias[col]; v1 += bias[col + 1]; }
                if (MODE == 0 && res) {
                    const float2 rr = *(const float2*)(res + (size_t)r * ldC + col);
                    v0 += rr.x; v1 += rr.y;
                }
                if (RELU) { v0 = fmaxf(v0, 0.f); v1 = fmaxf(v1, 0.f); }
                *(float2*)(C + (size_t)r * ldC + col) = make_float2(v0, v1);
            }
        }
    }
}

// ---------------- transpose: out[C,R] = in[R,C]^T ---------------------------
__global__ void transpose_k(const float* __restrict__ in, float* __restrict__ out,
                            int R, int C, size_t sIn, size_t sOut)
{
    in  += blockIdx.z * sIn;
    out += blockIdx.z * sOut;
    __shared__ float t[32][33];
    int x = blockIdx.x * 32 + threadIdx.x;
    int y = blockIdx.y * 32 + threadIdx.y;
#pragma unroll
    for (int j = 0; j < 32; j += 8)
        t[threadIdx.y + j][threadIdx.x] = in[(size_t)(y + j) * C + x];
    __syncthreads();
    x = blockIdx.y * 32 + threadIdx.x;
    y = blockIdx.x * 32 + threadIdx.y;
#pragma unroll
    for (int j = 0; j < 32; j += 8)
        out[(size_t)(y + j) * R + x] = t[threadIdx.x][threadIdx.y + j];
}

// ---------------- LayerNorm (torch semantics: ddof=1, eps on std) -----------
__global__ void ln_kernel(const float* __restrict__ x,
                          const float* __restrict__ g,
                          const float* __restrict__ be,
                          float* __restrict__ y)
{
    int row = blockIdx.x;
    const float* xr = x + (size_t)row * DIM;
    int t = threadIdx.x;
    __shared__ float red[256];

    float v[4];
    float s = 0.f;
#pragma unroll
    for (int i = 0; i < 4; i++) { v[i] = xr[t + 256 * i]; s += v[i]; }
    red[t] = s; __syncthreads();
    for (int st = 128; st > 0; st >>= 1) {
        if (t < st) red[t] += red[t + st];
        __syncthreads();
    }
    float mean = red[0] * (1.0f / DIM);
    __syncthreads();

    float qv = 0.f;
#pragma unroll
    for (int i = 0; i < 4; i++) { float d = v[i] - mean; qv += d * d; }
    red[t] = qv; __syncthreads();
    for (int st = 128; st > 0; st >>= 1) {
        if (t < st) red[t] += red[t + st];
        __syncthreads();
    }
    float stdv = sqrtf(red[0] / (float)(DIM - 1));
    float inv  = 1.0f / (stdv + 1e-6f);

    float* yr = y + (size_t)row * DIM;
#pragma unroll
    for (int i = 0; i < 4; i++) {
        int idx = t + 256 * i;
        yr[idx] = g[idx] * (v[i] - mean) * inv + be[idx];
    }
}

// ---------------- causal softmax (row); zero-fill to causal block end -------
__global__ void softmax_kernel(float* __restrict__ scores)
{
    int row = blockIdx.x;
    int b = row >> 11;
    int s = row & (SEQ - 1);
    float* p = scores + (size_t)b * SEQ * SEQ + (size_t)s * SEQ;
    int cnt = s + 1;
    int blockEnd = ((s >> 7) + 1) << 7;        // next 128 boundary (= AV K-limit)
    int t = threadIdx.x;
    __shared__ float red[256];

    float mx = -INFINITY;
    for (int j = t; j < cnt; j += 256) mx = fmaxf(mx, p[j]);
    red[t] = mx; __syncthreads();
    for (int st = 128; st > 0; st >>= 1) {
        if (t < st) red[t] = fmaxf(red[t], red[t + st]);
        __syncthreads();
    }
    mx = red[0]; __syncthreads();

    float sum = 0.f;
    for (int j = t; j < cnt; j += 256) {
        float e = __expf(p[j] - mx);
        p[j] = e;
        sum += e;
    }
    red[t] = sum; __syncthreads();
    for (int st = 128; st > 0; st >>= 1) {
        if (t < st) red[t] += red[t + st];
        __syncthreads();
    }
    float inv = 1.0f / red[0];

    for (int j = t; j < cnt; j += 256) p[j] *= inv;
    for (int j = cnt + t; j < blockEnd; j += 256) p[j] = 0.f;
}

// ---------------- launch -----------------------------------------------------
extern "C" void kernel_launch(void* const* d_in, const int* in_sizes, int n_in,
                              void* d_out, int out_size)
{
    const float* x   = (const float*)d_in[0];
    const float* wq  = (const float*)d_in[1];
    const float* bq  = (const float*)d_in[2];
    const float* wk  = (const float*)d_in[3];
    const float* bk  = (const float*)d_in[4];
    const float* wv  = (const float*)d_in[5];
    const float* bv  = (const float*)d_in[6];
    const float* wo  = (const float*)d_in[7];
    const float* bo  = (const float*)d_in[8];
    const float* w1  = (const float*)d_in[9];
    const float* b1  = (const float*)d_in[10];
    const float* w2  = (const float*)d_in[11];
    const float* b2  = (const float*)d_in[12];
    const float* g1  = (const float*)d_in[13];
    const float* be1 = (const float*)d_in[14];
    const float* g2  = (const float*)d_in[15];
    const float* be2 = (const float*)d_in[16];
    float* out = (float*)d_out;

    float *ln1, *q, *k, *v, *ctx, *h, *ln2, *mlp1, *sc, *wt, *vt;
    cudaGetSymbolAddress((void**)&ln1,  g_ln1);
    cudaGetSymbolAddress((void**)&q,    g_q);
    cudaGetSymbolAddress((void**)&k,    g_k);
    cudaGetSymbolAddress((void**)&v,    g_v);
    cudaGetSymbolAddress((void**)&ctx,  g_ctx);
    cudaGetSymbolAddress((void**)&h,    g_h);
    cudaGetSymbolAddress((void**)&ln2,  g_ln2);
    cudaGetSymbolAddress((void**)&mlp1, g_mlp1);
    cudaGetSymbolAddress((void**)&sc,   g_sc);
    cudaGetSymbolAddress((void**)&wt,   g_wt);
    cudaGetSymbolAddress((void**)&vt,   g_vt);

    float* wqt = wt + 0 * DIM * DIM;
    float* wkt = wt + 1 * DIM * DIM;
    float* wvt = wt + 2 * DIM * DIM;
    float* wot = wt + 3 * DIM * DIM;
    float* w1t = wt + 4 * DIM * DIM;
    float* w2t = wt + 5 * DIM * DIM;

    dim3 blk(256);
    dim3 gD(DIM / BN, ROWS / BM, 1);        // dense: (16, 64)
    dim3 gQK(SEQ / BN, SEQ / BM, BATCH);    // (32,16,4)
    dim3 gAV(DIM / BN, SEQ / BM, BATCH);    // (16,16,4)
    dim3 tblk(32, 8);
    dim3 tW(DIM / 32, DIM / 32, 1);
    dim3 tV(DIM / 32, SEQ / 32, BATCH);

    // LN1
    ln_kernel<<<ROWS, 256>>>(x, g1, be1, ln1);
    // weight transposes (B operand must be [N,K])
    transpose_k<<<tW, tblk>>>(wq, wqt, DIM, DIM, 0, 0);
    transpose_k<<<tW, tblk>>>(wk, wkt, DIM, DIM, 0, 0);
    transpose_k<<<tW, tblk>>>(wv, wvt, DIM, DIM, 0, 0);
    transpose_k<<<tW, tblk>>>(wo, wot, DIM, DIM, 0, 0);
    transpose_k<<<tW, tblk>>>(w1, w1t, DIM, DIM, 0, 0);
    transpose_k<<<tW, tblk>>>(w2, w2t, DIM, DIM, 0, 0);
    // Q, K, V projections
    hmma_gemm<0, false><<<gD, blk>>>(ln1, wqt, bq, nullptr, q, DIM, DIM, DIM, DIM, 0, 0, 0);
    hmma_gemm<0, false><<<gD, blk>>>(ln1, wkt, bk, nullptr, k, DIM, DIM, DIM, DIM, 0, 0, 0);
    hmma_gemm<0, false><<<gD, blk>>>(ln1, wvt, bv, nullptr, v, DIM, DIM, DIM, DIM, 0, 0, 0);
    // scores = Q K^T / sqrt(S)  (causal block skip)
    hmma_gemm<1, false><<<gQK, blk>>>(q, k, nullptr, nullptr, sc, DIM, DIM, DIM, SEQ,
                                      (size_t)SEQ * DIM, (size_t)SEQ * DIM, (size_t)SEQ * SEQ);
    // softmax
    softmax_kernel<<<ROWS, 256>>>(sc);
    // V^T per batch: [S,D] -> [D,S]
    transpose_k<<<tV, tblk>>>(v, vt, SEQ, DIM, (size_t)SEQ * DIM, (size_t)SEQ * DIM);
    // ctx = P V  (B = Vt[N=D, K=S]; causal K-limit)
    hmma_gemm<2, false><<<gAV, blk>>>(sc, vt, nullptr, nullptr, ctx, SEQ, SEQ, SEQ, DIM,
                                      (size_t)SEQ * SEQ, (size_t)SEQ * DIM, (size_t)SEQ * DIM);
    // h = ctx@wo + bo + x
    hmma_gemm<0, false><<<gD, blk>>>(ctx, wot, bo, x, h, DIM, DIM, DIM, DIM, 0, 0, 0);
    // LN2
    ln_kernel<<<ROWS, 256>>>(h, g2, be2, ln2);
    // mlp1 = relu(ln2@w1 + b1)
    hmma_gemm<0, true><<<gD, blk>>>(ln2, w1t, b1, nullptr, mlp1, DIM, DIM, DIM, DIM, 0, 0, 0);
    // out = mlp1@w2 + b2 + h
    hmma_gemm<0, false><<<gD, blk>>>(mlp1, w2t, b2, h, out, DIM, DIM, DIM, DIM, 0, 0, 0);
}

// round 5
// speedup vs baseline: 3.8940x; 1.2800x over previous
#include <cuda_runtime.h>
#include <cuda_bf16.h>
#include <stdint.h>
#include <math.h>

// Problem shape (fixed): B=4, S=2048, D=1024
#define BATCH 4
#define SEQ   2048
#define DIM   1024
#define ROWS  (BATCH*SEQ)          // 8192
#define QK_SCALE 0.0220970869f     // 1/sqrt(2048)

// GEMM tiling: CTA 128x64, K-chunk 64; 8 warps -> warp tile 32x32
#define BM 128
#define BN 64
#define BK 64
#define STAGE_BYTES 49152          // Ah 16K | Al 16K | Bh 8K | Bl 8K

typedef __nv_bfloat16 bf16;

// ---------------- scratch (device globals; no allocation allowed) -----------
__device__ bf16  g_ln1h[ROWS*DIM], g_ln1l[ROWS*DIM];
__device__ bf16  g_qh  [ROWS*DIM], g_ql  [ROWS*DIM];
__device__ bf16  g_kh  [ROWS*DIM], g_kl  [ROWS*DIM];
__device__ float g_v   [ROWS*DIM];
__device__ bf16  g_vth [ROWS*DIM], g_vtl [ROWS*DIM];
__device__ bf16  g_ctxh[ROWS*DIM], g_ctxl[ROWS*DIM];
__device__ float g_h   [ROWS*DIM];
__device__ bf16  g_ln2h[ROWS*DIM], g_ln2l[ROWS*DIM];
__device__ bf16  g_m1h [ROWS*DIM], g_m1l [ROWS*DIM];
__device__ float g_sc  [(size_t)BATCH*SEQ*SEQ];            // fp32 scores (64MB)
__device__ bf16  g_sch [(size_t)BATCH*SEQ*SEQ], g_scl[(size_t)BATCH*SEQ*SEQ];
__device__ bf16  g_wth [6*DIM*DIM], g_wtl[6*DIM*DIM];      // transposed weights

// ======================= helpers =============================================
__device__ __forceinline__ uint32_t smem_u32(const void* p) {
    uint32_t a;
    asm("{ .reg .u64 t; cvta.to.shared.u64 t, %1; cvt.u32.u64 %0, t; }"
        : "=r"(a) : "l"(p));
    return a;
}
__device__ __forceinline__ uint32_t sw128(uint32_t o) { return o ^ ((o >> 3) & 0x70); }

__device__ __forceinline__ void cp16(uint32_t dst, const void* src) {
    asm volatile("cp.async.cg.shared.global [%0], [%1], 16;"
                 :: "r"(dst), "l"(src) : "memory");
}

// split fp32 pair -> packed bf16x2 hi + lo(residual)
__device__ __forceinline__ void bf16_split2(float x, float y,
                                            uint32_t& hi, uint32_t& lo) {
    asm("cvt.rn.bf16x2.f32 %0, %1, %2;" : "=r"(hi) : "f"(y), "f"(x));
    float hx = __uint_as_float(hi << 16);
    float hy = __uint_as_float(hi & 0xffff0000u);
    float lx = x - hx, ly = y - hy;
    asm("cvt.rn.bf16x2.f32 %0, %1, %2;" : "=r"(lo) : "f"(ly), "f"(lx));
}
__device__ __forceinline__ void bf16_split1(float v, bf16& h, bf16& l) {
    h = __float2bfloat16(v);
    l = __float2bfloat16(v - __bfloat162float(h));
}

__device__ __forceinline__ void ldsm_x4(uint32_t* r, uint32_t addr) {
    asm volatile("ldmatrix.sync.aligned.m8n8.x4.shared.b16 {%0,%1,%2,%3}, [%4];"
                 : "=r"(r[0]), "=r"(r[1]), "=r"(r[2]), "=r"(r[3]) : "r"(addr));
}
__device__ __forceinline__ void mma16816(float* c, const uint32_t* a,
                                         uint32_t b0, uint32_t b1) {
    asm volatile("mma.sync.aligned.m16n8k16.row.col.f32.bf16.bf16.f32 "
                 "{%0,%1,%2,%3}, {%4,%5,%6,%7}, {%8,%9}, {%0,%1,%2,%3};"
                 : "+f"(c[0]), "+f"(c[1]), "+f"(c[2]), "+f"(c[3])
                 : "r"(a[0]), "r"(a[1]), "r"(a[2]), "r"(a[3]), "r"(b0), "r"(b1));
}

// ============ HMMA bf16x3 GEMM on pre-split planes ==========================
// C[M,N] = A[M,K] @ B[N,K]^T  where A = Ah+Al, B = Bh+Bl (drop lo*lo)
// MODE: 0=dense, 1=QK (scale, causal block-skip), 2=AV (causal K-limit)
// OUTP: 0 -> fp32 C (+bias,+res,RELU), 1 -> bf16 hi/lo planes (+bias,RELU)
template<int MODE, bool RELU, int OUTP>
__global__ void __launch_bounds__(256, 2)
hmma_gemm(const bf16* __restrict__ Ah, const bf16* __restrict__ Al,
          const bf16* __restrict__ Bh, const bf16* __restrict__ Bl,
          const float* __restrict__ bias, const float* __restrict__ res,
          float* __restrict__ C, bf16* __restrict__ Ch, bf16* __restrict__ Cl,
          int K, int ldA, int ldB, int ldC,
          size_t sA, size_t sB, size_t sC)
{
    int cRow = blockIdx.y * BM;
    int cCol = blockIdx.x * BN;
    if (MODE == 1 && cCol > cRow + BM - 1) return;   // fully above diagonal

    Ah += blockIdx.z * sA;  Al += blockIdx.z * sA;
    Bh += blockIdx.z * sB;  Bl += blockIdx.z * sB;
    if (OUTP == 0) { C += blockIdx.z * sC; if (res) res += blockIdx.z * sC; }
    else           { Ch += blockIdx.z * sC; Cl += blockIdx.z * sC; }

    int nc = (MODE == 2) ? (cRow + BM) / BK : K / BK;

    extern __shared__ __align__(1024) char smem[];
    uint32_t base = smem_u32(smem);

    int tid = threadIdx.x, lane = tid & 31, wid = tid >> 5;
    int wm = wid >> 1, wn = wid & 1;      // 4x2 warp grid, warp tile 32x32

    // stage K-chunk c into buffer buf (pure bf16 cp.async, swizzled)
    auto stage = [&](int c, int buf) {
        int kt = c * BK;
        uint32_t sb = base + buf * STAGE_BYTES;
#pragma unroll
        for (int i = 0; i < 4; i++) {                 // A planes: 1024 granules
            int g = tid + i * 256;
            int row = g >> 3, cc = g & 7;
            size_t go = (size_t)(cRow + row) * ldA + kt;
            uint32_t off = sw128((uint32_t)(row * 128 + cc * 16));
            cp16(sb + off,         (const char*)(Ah + go) + cc * 16);
            cp16(sb + 16384 + off, (const char*)(Al + go) + cc * 16);
        }
#pragma unroll
        for (int i = 0; i < 2; i++) {                 // B planes: 512 granules
            int g = tid + i * 256;
            int row = g >> 3, cc = g & 7;
            size_t go = (size_t)(cCol + row) * ldB + kt;
            uint32_t off = sw128((uint32_t)(row * 128 + cc * 16));
            cp16(sb + 32768 + off, (const char*)(Bh + go) + cc * 16);
            cp16(sb + 40960 + off, (const char*)(Bl + go) + cc * 16);
        }
        asm volatile("cp.async.commit_group;" ::: "memory");
    };

    float acc[2][4][4];
#pragma unroll
    for (int mi = 0; mi < 2; mi++)
#pragma unroll
        for (int ni = 0; ni < 4; ni++)
#pragma unroll
            for (int j = 0; j < 4; j++) acc[mi][ni][j] = 0.f;

    // per-thread ldmatrix offsets
    int a_r  = (lane & 15);
    int a_kb = (lane >> 4) << 4;
    int b_n  = (lane & 7) + ((lane >> 4) << 3);
    int b_kb = ((lane >> 3) & 1) << 4;

    stage(0, 0);
    for (int c = 0; c < nc; c++) {
        if (c + 1 < nc) {
            stage(c + 1, (c + 1) & 1);
            asm volatile("cp.async.wait_group 1;" ::: "memory");
        } else {
            asm volatile("cp.async.wait_group 0;" ::: "memory");
        }
        __syncthreads();

        uint32_t sb  = base + (c & 1) * STAGE_BYTES;
        uint32_t aHi = sb, aLo = sb + 16384, bHi = sb + 32768, bLo = sb + 40960;
#pragma unroll
        for (int ks = 0; ks < 4; ks++) {
            uint32_t ah[2][4], al[2][4];
#pragma unroll
            for (int mi = 0; mi < 2; mi++) {
                int r = wm * 32 + mi * 16 + a_r;
                uint32_t off = sw128((uint32_t)(r * 128 + ks * 32 + a_kb));
                ldsm_x4(ah[mi], aHi + off);
                ldsm_x4(al[mi], aLo + off);
            }
            uint32_t bh[2][4], bl[2][4];
#pragma unroll
            for (int np = 0; np < 2; np++) {
                int n = wn * 32 + np * 16 + b_n;
                uint32_t off = sw128((uint32_t)(n * 128 + ks * 32 + b_kb));
                ldsm_x4(bh[np], bHi + off);
                ldsm_x4(bl[np], bLo + off);
            }
#pragma unroll
            for (int mi = 0; mi < 2; mi++)
#pragma unroll
                for (int ni = 0; ni < 4; ni++) {
                    int np = ni >> 1, hf = (ni & 1) * 2;
                    mma16816(acc[mi][ni], ah[mi], bh[np][hf], bh[np][hf + 1]);
                    mma16816(acc[mi][ni], ah[mi], bl[np][hf], bl[np][hf + 1]);
                    mma16816(acc[mi][ni], al[mi], bh[np][hf], bh[np][hf + 1]);
                }
        }
        __syncthreads();
    }

    // ---- epilogue ----
#pragma unroll
    for (int mi = 0; mi < 2; mi++) {
#pragma unroll
        for (int ni = 0; ni < 4; ni++) {
            int row0 = cRow + wm * 32 + mi * 16 + (lane >> 2);
            int col  = cCol + wn * 32 + ni * 8 + (lane & 3) * 2;
#pragma unroll
            for (int hh = 0; hh < 2; hh++) {
                int r = row0 + hh * 8;
                float v0 = acc[mi][ni][hh * 2];
                float v1 = acc[mi][ni][hh * 2 + 1];
                if (MODE == 1) { v0 *= QK_SCALE; v1 *= QK_SCALE; }
                if (bias) { v0 += bias[col]; v1 += bias[col + 1]; }
                if (OUTP == 0 && res) {
                    const float2 rr = *(const float2*)(res + (size_t)r * ldC + col);
                    v0 += rr.x; v1 += rr.y;
                }
                if (RELU) { v0 = fmaxf(v0, 0.f); v1 = fmaxf(v1, 0.f); }
                if (OUTP == 0) {
                    *(float2*)(C + (size_t)r * ldC + col) = make_float2(v0, v1);
                } else {
                    uint32_t hi, lo;
                    bf16_split2(v0, v1, hi, lo);
                    *(uint32_t*)(Ch + (size_t)r * ldC + col) = hi;
                    *(uint32_t*)(Cl + (size_t)r * ldC + col) = lo;
                }
            }
        }
    }
}

// ---------------- transpose+split: out planes[C,R] = split(in[R,C]^T) -------
__global__ void transpose_split(const float* __restrict__ in,
                                bf16* __restrict__ oh, bf16* __restrict__ ol,
                                int R, int C, size_t sIn, size_t sOut)
{
    in += blockIdx.z * sIn;
    oh += blockIdx.z * sOut;
    ol += blockIdx.z * sOut;
    __shared__ float t[32][33];
    int x = blockIdx.x * 32 + threadIdx.x;
    int y = blockIdx.y * 32 + threadIdx.y;
#pragma unroll
    for (int j = 0; j < 32; j += 8)
        t[threadIdx.y + j][threadIdx.x] = in[(size_t)(y + j) * C + x];
    __syncthreads();
    x = blockIdx.y * 32 + threadIdx.x;
    y = blockIdx.x * 32 + threadIdx.y;
#pragma unroll
    for (int j = 0; j < 32; j += 8) {
        float v = t[threadIdx.x][threadIdx.y + j];
        bf16 h, l;
        bf16_split1(v, h, l);
        size_t o = (size_t)(y + j) * R + x;
        oh[o] = h; ol[o] = l;
    }
}

// ---------------- LayerNorm -> bf16 planes (ddof=1, eps on std) -------------
__global__ void ln_split(const float* __restrict__ x,
                         const float* __restrict__ g,
                         const float* __restrict__ be,
                         bf16* __restrict__ yh, bf16* __restrict__ yl)
{
    int row = blockIdx.x;
    const float* xr = x + (size_t)row * DIM;
    int t = threadIdx.x;
    __shared__ float red[256];

    float v[4];
    float s = 0.f;
#pragma unroll
    for (int i = 0; i < 4; i++) { v[i] = xr[t + 256 * i]; s += v[i]; }
    red[t] = s; __syncthreads();
    for (int st = 128; st > 0; st >>= 1) {
        if (t < st) red[t] += red[t + st];
        __syncthreads();
    }
    float mean = red[0] * (1.0f / DIM);
    __syncthreads();

    float qv = 0.f;
#pragma unroll
    for (int i = 0; i < 4; i++) { float d = v[i] - mean; qv += d * d; }
    red[t] = qv; __syncthreads();
    for (int st = 128; st > 0; st >>= 1) {
        if (t < st) red[t] += red[t + st];
        __syncthreads();
    }
    float stdv = sqrtf(red[0] / (float)(DIM - 1));
    float inv  = 1.0f / (stdv + 1e-6f);

#pragma unroll
    for (int i = 0; i < 4; i++) {
        int idx = t + 256 * i;
        float val = g[idx] * (v[i] - mean) * inv + be[idx];
        bf16 h, l;
        bf16_split1(val, h, l);
        yh[(size_t)row * DIM + idx] = h;
        yl[(size_t)row * DIM + idx] = l;
    }
}

// ------- causal softmax: fp32 scores -> bf16 prob planes (zero-filled) ------
__global__ void softmax_split(const float* __restrict__ scores,
                              bf16* __restrict__ ph, bf16* __restrict__ pl)
{
    int row = blockIdx.x;
    int b = row >> 11;
    int s = row & (SEQ - 1);
    size_t off = (size_t)b * SEQ * SEQ + (size_t)s * SEQ;
    const float* p = scores + off;
    int cnt = s + 1;
    int blockEnd = ((s >> 7) + 1) << 7;        // next 128 boundary (AV K-limit)
    int t = threadIdx.x;
    __shared__ float red[256];

    float mx = -INFINITY;
    for (int j = t; j < cnt; j += 256) mx = fmaxf(mx, p[j]);
    red[t] = mx; __syncthreads();
    for (int st = 128; st > 0; st >>= 1) {
        if (t < st) red[t] = fmaxf(red[t], red[t + st]);
        __syncthreads();
    }
    mx = red[0]; __syncthreads();

    float sum = 0.f;
    for (int j = t; j < cnt; j += 256) sum += __expf(p[j] - mx);
    red[t] = sum; __syncthreads();
    for (int st = 128; st > 0; st >>= 1) {
        if (t < st) red[t] += red[t + st];
        __syncthreads();
    }
    float inv = 1.0f / red[0];

    for (int j = t; j < cnt; j += 256) {
        float e = __expf(p[j] - mx) * inv;
        bf16 h, l;
        bf16_split1(e, h, l);
        ph[off + j] = h; pl[off + j] = l;
    }
    for (int j = cnt + t; j < blockEnd; j += 256) {
        ph[off + j] = __float2bfloat16(0.f);
        pl[off + j] = __float2bfloat16(0.f);
    }
}

// ---------------- launch -----------------------------------------------------
extern "C" void kernel_launch(void* const* d_in, const int* in_sizes, int n_in,
                              void* d_out, int out_size)
{
    const float* x   = (const float*)d_in[0];
    const float* wq  = (const float*)d_in[1];
    const float* bq  = (const float*)d_in[2];
    const float* wk  = (const float*)d_in[3];
    const float* bk  = (const float*)d_in[4];
    const float* wv  = (const float*)d_in[5];
    const float* bv  = (const float*)d_in[6];
    const float* wo  = (const float*)d_in[7];
    const float* bo  = (const float*)d_in[8];
    const float* w1  = (const float*)d_in[9];
    const float* b1  = (const float*)d_in[10];
    const float* w2  = (const float*)d_in[11];
    const float* b2  = (const float*)d_in[12];
    const float* g1  = (const float*)d_in[13];
    const float* be1 = (const float*)d_in[14];
    const float* g2  = (const float*)d_in[15];
    const float* be2 = (const float*)d_in[16];
    float* out = (float*)d_out;

    bf16 *ln1h, *ln1l, *qh, *ql, *kh, *kl, *vth, *vtl, *ctxh, *ctxl;
    bf16 *ln2h, *ln2l, *m1h, *m1l, *sch, *scl, *wth, *wtl;
    float *v, *h, *sc;
    cudaGetSymbolAddress((void**)&ln1h, g_ln1h);
    cudaGetSymbolAddress((void**)&ln1l, g_ln1l);
    cudaGetSymbolAddress((void**)&qh,   g_qh);
    cudaGetSymbolAddress((void**)&ql,   g_ql);
    cudaGetSymbolAddress((void**)&kh,   g_kh);
    cudaGetSymbolAddress((void**)&kl,   g_kl);
    cudaGetSymbolAddress((void**)&v,    g_v);
    cudaGetSymbolAddress((void**)&vth,  g_vth);
    cudaGetSymbolAddress((void**)&vtl,  g_vtl);
    cudaGetSymbolAddress((void**)&ctxh, g_ctxh);
    cudaGetSymbolAddress((void**)&ctxl, g_ctxl);
    cudaGetSymbolAddress((void**)&h,    g_h);
    cudaGetSymbolAddress((void**)&ln2h, g_ln2h);
    cudaGetSymbolAddress((void**)&ln2l, g_ln2l);
    cudaGetSymbolAddress((void**)&m1h,  g_m1h);
    cudaGetSymbolAddress((void**)&m1l,  g_m1l);
    cudaGetSymbolAddress((void**)&sc,   g_sc);
    cudaGetSymbolAddress((void**)&sch,  g_sch);
    cudaGetSymbolAddress((void**)&scl,  g_scl);
    cudaGetSymbolAddress((void**)&wth,  g_wth);
    cudaGetSymbolAddress((void**)&wtl,  g_wtl);

    bf16* wqth = wth + 0 * DIM * DIM;  bf16* wqtl = wtl + 0 * DIM * DIM;
    bf16* wkth = wth + 1 * DIM * DIM;  bf16* wktl = wtl + 1 * DIM * DIM;
    bf16* wvth = wth + 2 * DIM * DIM;  bf16* wvtl = wtl + 2 * DIM * DIM;
    bf16* woth = wth + 3 * DIM * DIM;  bf16* wotl = wtl + 3 * DIM * DIM;
    bf16* w1th = wth + 4 * DIM * DIM;  bf16* w1tl = wtl + 4 * DIM * DIM;
    bf16* w2th = wth + 5 * DIM * DIM;  bf16* w2tl = wtl + 5 * DIM * DIM;

    const int SMEM = 2 * STAGE_BYTES;   // 96KB
    cudaFuncSetAttribute(hmma_gemm<0, false, 0>, cudaFuncAttributeMaxDynamicSharedMemorySize, SMEM);
    cudaFuncSetAttribute(hmma_gemm<0, false, 1>, cudaFuncAttributeMaxDynamicSharedMemorySize, SMEM);
    cudaFuncSetAttribute(hmma_gemm<0, true,  1>, cudaFuncAttributeMaxDynamicSharedMemorySize, SMEM);
    cudaFuncSetAttribute(hmma_gemm<1, false, 0>, cudaFuncAttributeMaxDynamicSharedMemorySize, SMEM);
    cudaFuncSetAttribute(hmma_gemm<2, false, 1>, cudaFuncAttributeMaxDynamicSharedMemorySize, SMEM);

    dim3 blk(256);
    dim3 gD(DIM / BN, ROWS / BM, 1);        // dense: (16, 64)
    dim3 gQK(SEQ / BN, SEQ / BM, BATCH);    // (32,16,4)
    dim3 gAV(DIM / BN, SEQ / BM, BATCH);    // (16,16,4)
    dim3 tblk(32, 8);
    dim3 tW(DIM / 32, DIM / 32, 1);
    dim3 tV(DIM / 32, SEQ / 32, BATCH);

    // LN1 -> planes
    ln_split<<<ROWS, 256>>>(x, g1, be1, ln1h, ln1l);
    // weight transpose+split ([K,N] -> [N,K] planes)
    transpose_split<<<tW, tblk>>>(wq, wqth, wqtl, DIM, DIM, 0, 0);
    transpose_split<<<tW, tblk>>>(wk, wkth, wktl, DIM, DIM, 0, 0);
    transpose_split<<<tW, tblk>>>(wv, wvth, wvtl, DIM, DIM, 0, 0);
    transpose_split<<<tW, tblk>>>(wo, woth, wotl, DIM, DIM, 0, 0);
    transpose_split<<<tW, tblk>>>(w1, w1th, w1tl, DIM, DIM, 0, 0);
    transpose_split<<<tW, tblk>>>(w2, w2th, w2tl, DIM, DIM, 0, 0);
    // Q, K projections -> planes ; V projection -> fp32 (for transpose)
    hmma_gemm<0, false, 1><<<gD, blk, SMEM>>>(ln1h, ln1l, wqth, wqtl, bq, nullptr,
        nullptr, qh, ql, DIM, DIM, DIM, DIM, 0, 0, 0);
    hmma_gemm<0, false, 1><<<gD, blk, SMEM>>>(ln1h, ln1l, wkth, wktl, bk, nullptr,
        nullptr, kh, kl, DIM, DIM, DIM, DIM, 0, 0, 0);
    hmma_gemm<0, false, 0><<<gD, blk, SMEM>>>(ln1h, ln1l, wvth, wvtl, bv, nullptr,
        v, nullptr, nullptr, DIM, DIM, DIM, DIM, 0, 0, 0);
    // scores = Q K^T / sqrt(S)  (causal block skip) -> fp32
    hmma_gemm<1, false, 0><<<gQK, blk, SMEM>>>(qh, ql, kh, kl, nullptr, nullptr,
        sc, nullptr, nullptr, DIM, DIM, DIM, SEQ,
        (size_t)SEQ * DIM, (size_t)SEQ * DIM, (size_t)SEQ * SEQ);
    // softmax -> prob planes
    softmax_split<<<ROWS, 256>>>(sc, sch, scl);
    // V^T planes per batch: [S,D] -> [D,S]
    transpose_split<<<tV, tblk>>>(v, vth, vtl, SEQ, DIM,
                                  (size_t)SEQ * DIM, (size_t)SEQ * DIM);
    // ctx = P V  -> planes (causal K-limit)
    hmma_gemm<2, false, 1><<<gAV, blk, SMEM>>>(sch, scl, vth, vtl, nullptr, nullptr,
        nullptr, ctxh, ctxl, SEQ, SEQ, SEQ, DIM,
        (size_t)SEQ * SEQ, (size_t)SEQ * DIM, (size_t)SEQ * DIM);
    // h = ctx@wo + bo + x  -> fp32
    hmma_gemm<0, false, 0><<<gD, blk, SMEM>>>(ctxh, ctxl, woth, wotl, bo, x,
        h, nullptr, nullptr, DIM, DIM, DIM, DIM, 0, 0, 0);
    // LN2 -> planes
    ln_split<<<ROWS, 256>>>(h, g2, be2, ln2h, ln2l);
    // mlp1 = relu(ln2@w1 + b1) -> planes
    hmma_gemm<0, true, 1><<<gD, blk, SMEM>>>(ln2h, ln2l, w1th, w1tl, b1, nullptr,
        nullptr, m1h, m1l, DIM, DIM, DIM, DIM, 0, 0, 0);
    // out = mlp1@w2 + b2 + h  -> fp32
    hmma_gemm<0, false, 0><<<gD, blk, SMEM>>>(m1h, m1l, w2th, w2tl, b2, h,
        out, nullptr, nullptr, DIM, DIM, DIM, DIM, 0, 0, 0);
}

// round 6
// speedup vs baseline: 4.8222x; 1.2384x over previous
#include <cuda_runtime.h>
#include <cuda_bf16.h>
#include <stdint.h>
#include <math.h>

// Problem shape (fixed): B=4, S=2048, D=1024
#define BATCH 4
#define SEQ   2048
#define DIM   1024
#define ROWS  (BATCH*SEQ)          // 8192
#define QK_SCALE 0.0220970869f     // 1/sqrt(2048)

// GEMM tiling: CTA 128x64, K-chunk 64; 8 warps -> warp tile 32x32
#define BM 128
#define BN 64
#define BK 64
#define STAGE_BYTES 49152          // A 32K (128x64 fp32) | B 16K (64x64 fp32)

// ---------------- scratch (device globals; no allocation allowed) -----------
__device__ float g_ln1[ROWS*DIM];
__device__ float g_q  [ROWS*DIM];
__device__ float g_k  [ROWS*DIM];
__device__ float g_v  [ROWS*DIM];
__device__ float g_vt [ROWS*DIM];
__device__ float g_ctx[ROWS*DIM];
__device__ float g_h  [ROWS*DIM];
__device__ float g_ln2[ROWS*DIM];
__device__ float g_m1 [ROWS*DIM];
__device__ float g_sc [(size_t)BATCH*SEQ*SEQ];   // raw scores (64MB)
__device__ float g_sp [(size_t)BATCH*SEQ*SEQ];   // probs, tf32-rounded (64MB)
__device__ float g_wt [6*DIM*DIM];               // transposed weights (tf32)

// ======================= helpers =============================================
__device__ __forceinline__ uint32_t smem_u32(const void* p) {
    uint32_t a;
    asm("{ .reg .u64 t; cvta.to.shared.u64 t, %1; cvt.u32.u64 %0, t; }"
        : "=r"(a) : "l"(p));
    return a;
}
__device__ __forceinline__ float tf32r(float x) {
    float y;
    asm("cvt.rna.tf32.f32 %0, %1;" : "=f"(y) : "f"(x));
    return y;
}
__device__ __forceinline__ void cp16(uint32_t dst, const void* src) {
    asm volatile("cp.async.cg.shared.global [%0], [%1], 16;"
                 :: "r"(dst), "l"(src) : "memory");
}
// swizzled byte offset inside a tile with 256B rows; chunk = 16B unit (0..15)
__device__ __forceinline__ uint32_t swz(int row, int ch) {
    return (uint32_t)(row * 256 + (((ch & 8) | ((ch ^ row) & 7)) << 4));
}
__device__ __forceinline__ void ldsm_x4(uint32_t* r, uint32_t addr) {
    asm volatile("ldmatrix.sync.aligned.m8n8.x4.shared.b16 {%0,%1,%2,%3}, [%4];"
                 : "=r"(r[0]), "=r"(r[1]), "=r"(r[2]), "=r"(r[3]) : "r"(addr));
}
__device__ __forceinline__ void mma_tf32(float* c, const uint32_t* a,
                                         uint32_t b0, uint32_t b1) {
    asm volatile("mma.sync.aligned.m16n8k8.row.col.f32.tf32.tf32.f32 "
                 "{%0,%1,%2,%3}, {%4,%5,%6,%7}, {%8,%9}, {%0,%1,%2,%3};"
                 : "+f"(c[0]), "+f"(c[1]), "+f"(c[2]), "+f"(c[3])
                 : "r"(a[0]), "r"(a[1]), "r"(a[2]), "r"(a[3]), "r"(b0), "r"(b1));
}

// ============ tf32 HMMA GEMM: C[M,N] = A[M,K] @ B[N,K]^T =====================
// Operands must be pre-rounded to tf32 in gmem.
// MODE: 0=dense, 1=QK (scale, causal block-skip), 2=AV (causal K-limit)
// OUTP: 0 -> exact fp32 out (+res), 1 -> tf32-rounded fp32 out (feeds a GEMM)
template<int MODE, bool RELU, int OUTP>
__global__ void __launch_bounds__(256, 2)
tf32_gemm(const float* __restrict__ A, const float* __restrict__ B,
          const float* __restrict__ bias, const float* __restrict__ res,
          float* __restrict__ C, int K, int ldA, int ldB, int ldC,
          size_t sA, size_t sB, size_t sC)
{
    int cRow = blockIdx.y * BM;
    int cCol = blockIdx.x * BN;
    if (MODE == 1 && cCol > cRow + BM - 1) return;   // fully above diagonal

    A += blockIdx.z * sA;
    B += blockIdx.z * sB;
    C += blockIdx.z * sC;
    if (res) res += blockIdx.z * sC;

    int nc = (MODE == 2) ? (cRow + BM) / BK : K / BK;

    extern __shared__ __align__(1024) char smem[];
    uint32_t base = smem_u32(smem);

    int tid = threadIdx.x, lane = tid & 31, wid = tid >> 5;
    int wm = wid >> 1, wn = wid & 1;      // 4x2 warp grid, warp tile 32x32

    auto stage = [&](int c, int buf) {
        int kt = c * BK;
        uint32_t sb = base + buf * STAGE_BYTES;
#pragma unroll
        for (int i = 0; i < 8; i++) {                 // A: 2048 granules of 16B
            int g = tid + i * 256;
            int row = g >> 4, ch = g & 15;
            cp16(sb + swz(row, ch),
                 A + (size_t)(cRow + row) * ldA + kt + ch * 4);
        }
#pragma unroll
        for (int i = 0; i < 4; i++) {                 // B: 1024 granules
            int g = tid + i * 256;
            int row = g >> 4, ch = g & 15;
            cp16(sb + 32768 + swz(row, ch),
                 B + (size_t)(cCol + row) * ldB + kt + ch * 4);
        }
        asm volatile("cp.async.commit_group;" ::: "memory");
    };

    float acc[2][4][4];
#pragma unroll
    for (int mi = 0; mi < 2; mi++)
#pragma unroll
        for (int ni = 0; ni < 4; ni++)
#pragma unroll
            for (int j = 0; j < 4; j++) acc[mi][ni][j] = 0.f;

    // ldmatrix per-lane row/parity (fixed per thread)
    int lm = lane >> 3;        // matrix index 0..3
    int lr = lane & 7;         // row within matrix
    // A frag mi: row = wm*32 + mi*16 + (lm&1)*8 + lr ; chunk = 2ks + (lm>>1)
    int aRow0 = wm * 32 + (lm & 1) * 8 + lr;
    int aChP  = lm >> 1;
    // B pair pp: row = wn*32 + pp*16 + (lm>>1)*8 + lr ; chunk = 2ks + (lm&1)
    int bRow0 = wn * 32 + (lm >> 1) * 8 + lr;
    int bChP  = lm & 1;

    stage(0, 0);
    for (int c = 0; c < nc; c++) {
        if (c + 1 < nc) {
            stage(c + 1, (c + 1) & 1);
            asm volatile("cp.async.wait_group 1;" ::: "memory");
        } else {
            asm volatile("cp.async.wait_group 0;" ::: "memory");
        }
        __syncthreads();

        uint32_t sb = base + (c & 1) * STAGE_BYTES;
        uint32_t aB = sb, bB = sb + 32768;
#pragma unroll
        for (int ks = 0; ks < 8; ks++) {
            uint32_t a[2][4];
#pragma unroll
            for (int mi = 0; mi < 2; mi++)
                ldsm_x4(a[mi], aB + swz(aRow0 + mi * 16, 2 * ks + aChP));
            uint32_t b[2][4];
#pragma unroll
            for (int pp = 0; pp < 2; pp++)
                ldsm_x4(b[pp], bB + swz(bRow0 + pp * 16, 2 * ks + bChP));
#pragma unroll
            for (int mi = 0; mi < 2; mi++)
#pragma unroll
                for (int ni = 0; ni < 4; ni++) {
                    int pp = ni >> 1, o = (ni & 1) * 2;
                    mma_tf32(acc[mi][ni], a[mi], b[pp][o], b[pp][o + 1]);
                }
        }
        __syncthreads();
    }

    // ---- epilogue ----
#pragma unroll
    for (int mi = 0; mi < 2; mi++) {
#pragma unroll
        for (int ni = 0; ni < 4; ni++) {
            int row0 = cRow + wm * 32 + mi * 16 + (lane >> 2);
            int col  = cCol + wn * 32 + ni * 8 + (lane & 3) * 2;
#pragma unroll
            for (int hh = 0; hh < 2; hh++) {
                int r = row0 + hh * 8;
                float v0 = acc[mi][ni][hh * 2];
                float v1 = acc[mi][ni][hh * 2 + 1];
                if (MODE == 1) { v0 *= QK_SCALE; v1 *= QK_SCALE; }
                if (bias) { v0 += bias[col]; v1 += bias[col + 1]; }
                if (OUTP == 0 && res) {
                    const float2 rr = *(const float2*)(res + (size_t)r * ldC + col);
                    v0 += rr.x; v1 += rr.y;
                }
                if (RELU) { v0 = fmaxf(v0, 0.f); v1 = fmaxf(v1, 0.f); }
                if (OUTP == 1) { v0 = tf32r(v0); v1 = tf32r(v1); }
                *(float2*)(C + (size_t)r * ldC + col) = make_float2(v0, v1);
            }
        }
    }
}

// ------- transpose (+tf32 round): out[C,R] = round(in[R,C]^T) ---------------
__global__ void transpose_r(const float* __restrict__ in, float* __restrict__ out,
                            int R, int C, size_t sIn, size_t sOut)
{
    in  += blockIdx.z * sIn;
    out += blockIdx.z * sOut;
    __shared__ float t[32][33];
    int x = blockIdx.x * 32 + threadIdx.x;
    int y = blockIdx.y * 32 + threadIdx.y;
#pragma unroll
    for (int j = 0; j < 32; j += 8)
        t[threadIdx.y + j][threadIdx.x] = in[(size_t)(y + j) * C + x];
    __syncthreads();
    x = blockIdx.y * 32 + threadIdx.x;
    y = blockIdx.x * 32 + threadIdx.y;
#pragma unroll
    for (int j = 0; j < 32; j += 8)
        out[(size_t)(y + j) * R + x] = tf32r(t[threadIdx.x][threadIdx.y + j]);
}

// ------- LayerNorm -> tf32-rounded fp32 (ddof=1, eps on std) ----------------
__global__ void ln_kernel(const float* __restrict__ x,
                          const float* __restrict__ g,
                          const float* __restrict__ be,
                          float* __restrict__ y)
{
    int row = blockIdx.x;
    const float* xr = x + (size_t)row * DIM;
    int t = threadIdx.x;
    __shared__ float red[256];

    float v[4];
    float s = 0.f;
#pragma unroll
    for (int i = 0; i < 4; i++) { v[i] = xr[t + 256 * i]; s += v[i]; }
    red[t] = s; __syncthreads();
    for (int st = 128; st > 0; st >>= 1) {
        if (t < st) red[t] += red[t + st];
        __syncthreads();
    }
    float mean = red[0] * (1.0f / DIM);
    __syncthreads();

    float qv = 0.f;
#pragma unroll
    for (int i = 0; i < 4; i++) { float d = v[i] - mean; qv += d * d; }
    red[t] = qv; __syncthreads();
    for (int st = 128; st > 0; st >>= 1) {
        if (t < st) red[t] += red[t + st];
        __syncthreads();
    }
    float stdv = sqrtf(red[0] / (float)(DIM - 1));
    float inv  = 1.0f / (stdv + 1e-6f);

    float* yr = y + (size_t)row * DIM;
#pragma unroll
    for (int i = 0; i < 4; i++) {
        int idx = t + 256 * i;
        yr[idx] = tf32r(g[idx] * (v[i] - mean) * inv + be[idx]);
    }
}

// ------- causal softmax: sc -> tf32-rounded probs (zero-filled) -------------
__global__ void softmax_kernel(const float* __restrict__ scores,
                               float* __restrict__ probs)
{
    int row = blockIdx.x;
    int b = row >> 11;
    int s = row & (SEQ - 1);
    size_t off = (size_t)b * SEQ * SEQ + (size_t)s * SEQ;
    const float* p = scores + off;
    float* o = probs + off;
    int cnt = s + 1;
    int blockEnd = ((s >> 7) + 1) << 7;        // next 128 boundary (AV K-limit)
    int t = threadIdx.x;
    __shared__ float red[256];

    float mx = -INFINITY;
    for (int j = t; j < cnt; j += 256) mx = fmaxf(mx, p[j]);
    red[t] = mx; __syncthreads();
    for (int st = 128; st > 0; st >>= 1) {
        if (t < st) red[t] = fmaxf(red[t], red[t + st]);
        __syncthreads();
    }
    mx = red[0]; __syncthreads();

    float sum = 0.f;
    for (int j = t; j < cnt; j += 256) sum += __expf(p[j] - mx);
    red[t] = sum; __syncthreads();
    for (int st = 128; st > 0; st >>= 1) {
        if (t < st) red[t] += red[t + st];
        __syncthreads();
    }
    float inv = 1.0f / red[0];

    for (int j = t; j < cnt; j += 256) o[j] = tf32r(__expf(p[j] - mx) * inv);
    for (int j = cnt + t; j < blockEnd; j += 256) o[j] = 0.f;
}

// ---------------- launch -----------------------------------------------------
extern "C" void kernel_launch(void* const* d_in, const int* in_sizes, int n_in,
                              void* d_out, int out_size)
{
    const float* x   = (const float*)d_in[0];
    const float* wq  = (const float*)d_in[1];
    const float* bq  = (const float*)d_in[2];
    const float* wk  = (const float*)d_in[3];
    const float* bk  = (const float*)d_in[4];
    const float* wv  = (const float*)d_in[5];
    const float* bv  = (const float*)d_in[6];
    const float* wo  = (const float*)d_in[7];
    const float* bo  = (const float*)d_in[8];
    const float* w1  = (const float*)d_in[9];
    const float* b1  = (const float*)d_in[10];
    const float* w2  = (const float*)d_in[11];
    const float* b2  = (const float*)d_in[12];
    const float* g1  = (const float*)d_in[13];
    const float* be1 = (const float*)d_in[14];
    const float* g2  = (const float*)d_in[15];
    const float* be2 = (const float*)d_in[16];
    float* out = (float*)d_out;

    float *ln1, *q, *k, *v, *vt, *ctx, *h, *ln2, *m1, *sc, *sp, *wt;
    cudaGetSymbolAddress((void**)&ln1, g_ln1);
    cudaGetSymbolAddress((void**)&q,   g_q);
    cudaGetSymbolAddress((void**)&k,   g_k);
    cudaGetSymbolAddress((void**)&v,   g_v);
    cudaGetSymbolAddress((void**)&vt,  g_vt);
    cudaGetSymbolAddress((void**)&ctx, g_ctx);
    cudaGetSymbolAddress((void**)&h,   g_h);
    cudaGetSymbolAddress((void**)&ln2, g_ln2);
    cudaGetSymbolAddress((void**)&m1,  g_m1);
    cudaGetSymbolAddress((void**)&sc,  g_sc);
    cudaGetSymbolAddress((void**)&sp,  g_sp);
    cudaGetSymbolAddress((void**)&wt,  g_wt);

    float* wqt = wt + 0 * DIM * DIM;
    float* wkt = wt + 1 * DIM * DIM;
    float* wvt = wt + 2 * DIM * DIM;
    float* wot = wt + 3 * DIM * DIM;
    float* w1t = wt + 4 * DIM * DIM;
    float* w2t = wt + 5 * DIM * DIM;

    const int SMEM = 2 * STAGE_BYTES;   // 96KB
    cudaFuncSetAttribute(tf32_gemm<0, false, 0>, cudaFuncAttributeMaxDynamicSharedMemorySize, SMEM);
    cudaFuncSetAttribute(tf32_gemm<0, false, 1>, cudaFuncAttributeMaxDynamicSharedMemorySize, SMEM);
    cudaFuncSetAttribute(tf32_gemm<0, true,  1>, cudaFuncAttributeMaxDynamicSharedMemorySize, SMEM);
    cudaFuncSetAttribute(tf32_gemm<1, false, 0>, cudaFuncAttributeMaxDynamicSharedMemorySize, SMEM);
    cudaFuncSetAttribute(tf32_gemm<2, false, 1>, cudaFuncAttributeMaxDynamicSharedMemorySize, SMEM);

    dim3 blk(256);
    dim3 gD(DIM / BN, ROWS / BM, 1);        // dense: (16, 64)
    dim3 gQK(SEQ / BN, SEQ / BM, BATCH);    // (32,16,4)
    dim3 gAV(DIM / BN, SEQ / BM, BATCH);    // (16,16,4)
    dim3 tblk(32, 8);
    dim3 tW(DIM / 32, DIM / 32, 1);
    dim3 tV(DIM / 32, SEQ / 32, BATCH);

    // LN1 (tf32-rounded)
    ln_kernel<<<ROWS, 256>>>(x, g1, be1, ln1);
    // weight transposes ([K,N] -> [N,K], tf32-rounded)
    transpose_r<<<tW, tblk>>>(wq, wqt, DIM, DIM, 0, 0);
    transpose_r<<<tW, tblk>>>(wk, wkt, DIM, DIM, 0, 0);
    transpose_r<<<tW, tblk>>>(wv, wvt, DIM, DIM, 0, 0);
    transpose_r<<<tW, tblk>>>(wo, wot, DIM, DIM, 0, 0);
    transpose_r<<<tW, tblk>>>(w1, w1t, DIM, DIM, 0, 0);
    transpose_r<<<tW, tblk>>>(w2, w2t, DIM, DIM, 0, 0);
    // Q, K projections (rounded out); V projection exact fp32 (transpose rounds)
    tf32_gemm<0, false, 1><<<gD, blk, SMEM>>>(ln1, wqt, bq, nullptr, q,
        DIM, DIM, DIM, DIM, 0, 0, 0);
    tf32_gemm<0, false, 1><<<gD, blk, SMEM>>>(ln1, wkt, bk, nullptr, k,
        DIM, DIM, DIM, DIM, 0, 0, 0);
    tf32_gemm<0, false, 0><<<gD, blk, SMEM>>>(ln1, wvt, bv, nullptr, v,
        DIM, DIM, DIM, DIM, 0, 0, 0);
    // scores = Q K^T / sqrt(S)  (causal block skip)
    tf32_gemm<1, false, 0><<<gQK, blk, SMEM>>>(q, k, nullptr, nullptr, sc,
        DIM, DIM, DIM, SEQ,
        (size_t)SEQ * DIM, (size_t)SEQ * DIM, (size_t)SEQ * SEQ);
    // softmax -> rounded probs
    softmax_kernel<<<ROWS, 256>>>(sc, sp);
    // V^T per batch: [S,D] -> [D,S] (rounded)
    transpose_r<<<tV, tblk>>>(v, vt, SEQ, DIM,
                              (size_t)SEQ * DIM, (size_t)SEQ * DIM);
    // ctx = P V  (causal K-limit, rounded out)
    tf32_gemm<2, false, 1><<<gAV, blk, SMEM>>>(sp, vt, nullptr, nullptr, ctx,
        SEQ, SEQ, SEQ, DIM,
        (size_t)SEQ * SEQ, (size_t)SEQ * DIM, (size_t)SEQ * DIM);
    // h = ctx@wo + bo + x
    tf32_gemm<0, false, 0><<<gD, blk, SMEM>>>(ctx, wot, bo, x, h,
        DIM, DIM, DIM, DIM, 0, 0, 0);
    // LN2 (rounded)
    ln_kernel<<<ROWS, 256>>>(h, g2, be2, ln2);
    // mlp1 = relu(ln2@w1 + b1) (rounded out)
    tf32_gemm<0, true, 1><<<gD, blk, SMEM>>>(ln2, w1t, b1, nullptr, m1,
        DIM, DIM, DIM, DIM, 0, 0, 0);
    // out = mlp1@w2 + b2 + h
    tf32_gemm<0, false, 0><<<gD, blk, SMEM>>>(m1, w2t, b2, h, out,
        DIM, DIM, DIM, DIM, 0, 0, 0);
}

// round 7
// speedup vs baseline: 5.0058x; 1.0381x over previous
#include <cuda_runtime.h>
#include <cuda_bf16.h>
#include <stdint.h>
#include <math.h>

// Problem shape (fixed): B=4, S=2048, D=1024
#define BATCH 4
#define SEQ   2048
#define DIM   1024
#define ROWS  (BATCH*SEQ)          // 8192
#define QK_SCALE 0.0220970869f     // 1/sqrt(2048)

// GEMM tiling: CTA 128x64, K-chunk 64; 8 warps -> warp tile 32x32
#define BM 128
#define BN 64
#define BK 64
#define STAGE_BYTES 49152          // A 32K (128x64 fp32) | B 16K (64x64 fp32)

// ---------------- scratch (device globals; no allocation allowed) -----------
__device__ float g_ln1[ROWS*DIM];
__device__ float g_q  [ROWS*DIM];
__device__ float g_k  [ROWS*DIM];
__device__ float g_vt [ROWS*DIM];                // V^T per batch [D, S]
__device__ float g_ctx[ROWS*DIM];
__device__ float g_h  [ROWS*DIM];
__device__ float g_ln2[ROWS*DIM];
__device__ float g_m1 [ROWS*DIM];
__device__ float g_sc [(size_t)BATCH*SEQ*SEQ];   // raw scores (64MB)
__device__ float g_sp [(size_t)BATCH*SEQ*SEQ];   // probs, tf32-rounded (64MB)
__device__ float g_wt [6*DIM*DIM];               // transposed weights (tf32)

// ======================= helpers =============================================
__device__ __forceinline__ uint32_t smem_u32(const void* p) {
    uint32_t a;
    asm("{ .reg .u64 t; cvta.to.shared.u64 t, %1; cvt.u32.u64 %0, t; }"
        : "=r"(a) : "l"(p));
    return a;
}
__device__ __forceinline__ float tf32r(float x) {
    float y;
    asm("cvt.rna.tf32.f32 %0, %1;" : "=f"(y) : "f"(x));
    return y;
}
__device__ __forceinline__ void cp16(uint32_t dst, const void* src) {
    asm volatile("cp.async.cg.shared.global [%0], [%1], 16;"
                 :: "r"(dst), "l"(src) : "memory");
}
// swizzled byte offset inside a tile with 256B rows; chunk = 16B unit (0..15)
__device__ __forceinline__ uint32_t swz(int row, int ch) {
    return (uint32_t)(row * 256 + (((ch & 8) | ((ch ^ row) & 7)) << 4));
}
__device__ __forceinline__ void ldsm_x4(uint32_t* r, uint32_t addr) {
    asm volatile("ldmatrix.sync.aligned.m8n8.x4.shared.b16 {%0,%1,%2,%3}, [%4];"
                 : "=r"(r[0]), "=r"(r[1]), "=r"(r[2]), "=r"(r[3]) : "r"(addr));
}
__device__ __forceinline__ void mma_tf32(float* c, const uint32_t* a,
                                         uint32_t b0, uint32_t b1) {
    asm volatile("mma.sync.aligned.m16n8k8.row.col.f32.tf32.tf32.f32 "
                 "{%0,%1,%2,%3}, {%4,%5,%6,%7}, {%8,%9}, {%0,%1,%2,%3};"
                 : "+f"(c[0]), "+f"(c[1]), "+f"(c[2]), "+f"(c[3])
                 : "r"(a[0]), "r"(a[1]), "r"(a[2]), "r"(a[3]), "r"(b0), "r"(b1));
}

// ============ tf32 HMMA GEMM: C[M,N] = A[M,K] @ B[N,K]^T =====================
// Operands must be pre-rounded to tf32 in gmem.
// MODE: 0=dense, 1=QK (scale, causal block-skip), 2=AV (causal K-limit,
//       heavy-tiles-first scheduling)
// OUTP: 0 -> exact fp32 out (+res), 1 -> tf32-rounded fp32 out,
//       2 -> transposed tf32 out (C = base of [D, SEQ] per-batch tensor)
template<int MODE, bool RELU, int OUTP>
__global__ void __launch_bounds__(256, 2)
tf32_gemm(const float* __restrict__ A, const float* __restrict__ B,
          const float* __restrict__ bias, const float* __restrict__ res,
          float* __restrict__ C, int K, int ldA, int ldB, int ldC,
          size_t sA, size_t sB, size_t sC)
{
    int by = (MODE == 2) ? (gridDim.y - 1 - blockIdx.y) : blockIdx.y;
    int cRow = by * BM;
    int cCol = blockIdx.x * BN;
    if (MODE == 1 && cCol > cRow + BM - 1) return;   // fully above diagonal

    A += blockIdx.z * sA;
    B += blockIdx.z * sB;
    if (OUTP != 2) { C += blockIdx.z * sC; if (res) res += blockIdx.z * sC; }

    int nc = (MODE == 2) ? (cRow + BM) / BK : K / BK;

    extern __shared__ __align__(1024) char smem[];
    uint32_t base = smem_u32(smem);

    int tid = threadIdx.x, lane = tid & 31, wid = tid >> 5;
    int wm = wid >> 1, wn = wid & 1;      // 4x2 warp grid, warp tile 32x32

    auto stage = [&](int c, int buf) {
        int kt = c * BK;
        uint32_t sb = base + buf * STAGE_BYTES;
#pragma unroll
        for (int i = 0; i < 8; i++) {                 // A: 2048 granules of 16B
            int g = tid + i * 256;
            int row = g >> 4, ch = g & 15;
            cp16(sb + swz(row, ch),
                 A + (size_t)(cRow + row) * ldA + kt + ch * 4);
        }
#pragma unroll
        for (int i = 0; i < 4; i++) {                 // B: 1024 granules
            int g = tid + i * 256;
            int row = g >> 4, ch = g & 15;
            cp16(sb + 32768 + swz(row, ch),
                 B + (size_t)(cCol + row) * ldB + kt + ch * 4);
        }
        asm volatile("cp.async.commit_group;" ::: "memory");
    };

    float acc[2][4][4];
#pragma unroll
    for (int mi = 0; mi < 2; mi++)
#pragma unroll
        for (int ni = 0; ni < 4; ni++)
#pragma unroll
            for (int j = 0; j < 4; j++) acc[mi][ni][j] = 0.f;

    // ldmatrix per-lane row/parity (fixed per thread)
    int lm = lane >> 3;        // matrix index 0..3
    int lr = lane & 7;         // row within matrix
    int aRow0 = wm * 32 + (lm & 1) * 8 + lr;
    int aChP  = lm >> 1;
    int bRow0 = wn * 32 + (lm >> 1) * 8 + lr;
    int bChP  = lm & 1;

    stage(0, 0);
    for (int c = 0; c < nc; c++) {
        if (c + 1 < nc) {
            stage(c + 1, (c + 1) & 1);
            asm volatile("cp.async.wait_group 1;" ::: "memory");
        } else {
            asm volatile("cp.async.wait_group 0;" ::: "memory");
        }
        __syncthreads();

        uint32_t sb = base + (c & 1) * STAGE_BYTES;
        uint32_t aB = sb, bB = sb + 32768;
#pragma unroll
        for (int ks = 0; ks < 8; ks++) {
            uint32_t a[2][4];
#pragma unroll
            for (int mi = 0; mi < 2; mi++)
                ldsm_x4(a[mi], aB + swz(aRow0 + mi * 16, 2 * ks + aChP));
            uint32_t b[2][4];
#pragma unroll
            for (int pp = 0; pp < 2; pp++)
                ldsm_x4(b[pp], bB + swz(bRow0 + pp * 16, 2 * ks + bChP));
#pragma unroll
            for (int mi = 0; mi < 2; mi++)
#pragma unroll
                for (int ni = 0; ni < 4; ni++) {
                    int pp = ni >> 1, o = (ni & 1) * 2;
                    mma_tf32(acc[mi][ni], a[mi], b[pp][o], b[pp][o + 1]);
                }
        }
        __syncthreads();
    }

    // ---- epilogue ----
    if (OUTP == 2) {
        // transposed store: acc tile -> smem [col][row] -> coalesced Vt write
        float* ts = (float*)smem;                     // 64 x 132 floats
#pragma unroll
        for (int mi = 0; mi < 2; mi++)
#pragma unroll
            for (int ni = 0; ni < 4; ni++) {
                int rL = wm * 32 + mi * 16 + (lane >> 2);
                int cL = wn * 32 + ni * 8 + (lane & 3) * 2;
#pragma unroll
                for (int hh = 0; hh < 2; hh++) {
                    float v0 = acc[mi][ni][hh * 2];
                    float v1 = acc[mi][ni][hh * 2 + 1];
                    if (bias) { v0 += bias[cCol + cL]; v1 += bias[cCol + cL + 1]; }
                    ts[cL * 132 + rL + hh * 8]       = v0;
                    ts[(cL + 1) * 132 + rL + hh * 8] = v1;
                }
            }
        __syncthreads();
        int bb = cRow >> 11;                          // batch of this row block
        int s0 = cRow & (SEQ - 1);
        float* dst = C + (size_t)bb * SEQ * DIM;
#pragma unroll
        for (int i = 0; i < 8; i++) {
            int cc = wid * 8 + i;
            float4 o;
            o.x = tf32r(ts[cc * 132 + lane * 4 + 0]);
            o.y = tf32r(ts[cc * 132 + lane * 4 + 1]);
            o.z = tf32r(ts[cc * 132 + lane * 4 + 2]);
            o.w = tf32r(ts[cc * 132 + lane * 4 + 3]);
            *(float4*)(dst + (size_t)(cCol + cc) * SEQ + s0 + lane * 4) = o;
        }
        return;
    }

#pragma unroll
    for (int mi = 0; mi < 2; mi++) {
#pragma unroll
        for (int ni = 0; ni < 4; ni++) {
            int row0 = cRow + wm * 32 + mi * 16 + (lane >> 2);
            int col  = cCol + wn * 32 + ni * 8 + (lane & 3) * 2;
#pragma unroll
            for (int hh = 0; hh < 2; hh++) {
                int r = row0 + hh * 8;
                float v0 = acc[mi][ni][hh * 2];
                float v1 = acc[mi][ni][hh * 2 + 1];
                if (MODE == 1) { v0 *= QK_SCALE; v1 *= QK_SCALE; }
                if (bias) { v0 += bias[col]; v1 += bias[col + 1]; }
                if (OUTP == 0 && res) {
                    const float2 rr = *(const float2*)(res + (size_t)r * ldC + col);
                    v0 += rr.x; v1 += rr.y;
                }
                if (RELU) { v0 = fmaxf(v0, 0.f); v1 = fmaxf(v1, 0.f); }
                if (OUTP == 1) { v0 = tf32r(v0); v1 = tf32r(v1); }
                *(float2*)(C + (size_t)r * ldC + col) = make_float2(v0, v1);
            }
        }
    }
}

// ------- transpose (+tf32 round): out[C,R] = round(in[R,C]^T) ---------------
__global__ void transpose_r(const float* __restrict__ in, float* __restrict__ out,
                            int R, int C)
{
    __shared__ float t[32][33];
    int x = blockIdx.x * 32 + threadIdx.x;
    int y = blockIdx.y * 32 + threadIdx.y;
#pragma unroll
    for (int j = 0; j < 32; j += 8)
        t[threadIdx.y + j][threadIdx.x] = in[(size_t)(y + j) * C + x];
    __syncthreads();
    x = blockIdx.y * 32 + threadIdx.x;
    y = blockIdx.x * 32 + threadIdx.y;
#pragma unroll
    for (int j = 0; j < 32; j += 8)
        out[(size_t)(y + j) * R + x] = tf32r(t[threadIdx.x][threadIdx.y + j]);
}

// ------- LayerNorm -> tf32-rounded fp32 (ddof=1, eps on std) ----------------
__global__ void ln_kernel(const float* __restrict__ x,
                          const float* __restrict__ g,
                          const float* __restrict__ be,
                          float* __restrict__ y)
{
    int row = blockIdx.x;
    int t = threadIdx.x;
    __shared__ float red[256];

    float4 v = *(const float4*)(x + (size_t)row * DIM + t * 4);
    float s = v.x + v.y + v.z + v.w;
    red[t] = s; __syncthreads();
    for (int st = 128; st > 0; st >>= 1) {
        if (t < st) red[t] += red[t + st];
        __syncthreads();
    }
    float mean = red[0] * (1.0f / DIM);
    __syncthreads();

    float dx = v.x - mean, dy = v.y - mean, dz = v.z - mean, dw = v.w - mean;
    red[t] = dx * dx + dy * dy + dz * dz + dw * dw;
    __syncthreads();
    for (int st = 128; st > 0; st >>= 1) {
        if (t < st) red[t] += red[t + st];
        __syncthreads();
    }
    float stdv = sqrtf(red[0] / (float)(DIM - 1));
    float inv  = 1.0f / (stdv + 1e-6f);

    float4 gg = *(const float4*)(g + t * 4);
    float4 bb = *(const float4*)(be + t * 4);
    float4 o;
    o.x = tf32r(gg.x * dx * inv + bb.x);
    o.y = tf32r(gg.y * dy * inv + bb.y);
    o.z = tf32r(gg.z * dz * inv + bb.z);
    o.w = tf32r(gg.w * dw * inv + bb.w);
    *(float4*)(y + (size_t)row * DIM + t * 4) = o;
}

// ------- causal softmax (register row, single exp pass) ---------------------
__global__ void softmax_kernel(const float* __restrict__ scores,
                               float* __restrict__ probs)
{
    int row = blockIdx.x;
    int b = row >> 11;
    int s = row & (SEQ - 1);
    size_t off = (size_t)b * SEQ * SEQ + (size_t)s * SEQ;
    const float* p = scores + off;
    float* o = probs + off;
    int cnt = s + 1;
    int blockEnd = ((s >> 7) + 1) << 7;        // next 128 boundary (AV K-limit)
    int t = threadIdx.x;
    __shared__ float red[256];

    float e[8];
    float mx = -INFINITY;
#pragma unroll
    for (int i = 0; i < 8; i++) {
        int j = t + i * 256;
        e[i] = (j < cnt) ? p[j] : -INFINITY;
        mx = fmaxf(mx, e[i]);
    }
    red[t] = mx; __syncthreads();
    for (int st = 128; st > 0; st >>= 1) {
        if (t < st) red[t] = fmaxf(red[t], red[t + st]);
        __syncthreads();
    }
    mx = red[0]; __syncthreads();

    float sum = 0.f;
#pragma unroll
    for (int i = 0; i < 8; i++) {
        int j = t + i * 256;
        if (j < cnt) { e[i] = __expf(e[i] - mx); sum += e[i]; }
    }
    red[t] = sum; __syncthreads();
    for (int st = 128; st > 0; st >>= 1) {
        if (t < st) red[t] += red[t + st];
        __syncthreads();
    }
    float inv = 1.0f / red[0];

#pragma unroll
    for (int i = 0; i < 8; i++) {
        int j = t + i * 256;
        if (j < cnt) o[j] = tf32r(e[i] * inv);
    }
    for (int j = cnt + t; j < blockEnd; j += 256) o[j] = 0.f;
}

// ---------------- launch -----------------------------------------------------
extern "C" void kernel_launch(void* const* d_in, const int* in_sizes, int n_in,
                              void* d_out, int out_size)
{
    const float* x   = (const float*)d_in[0];
    const float* wq  = (const float*)d_in[1];
    const float* bq  = (const float*)d_in[2];
    const float* wk  = (const float*)d_in[3];
    const float* bk  = (const float*)d_in[4];
    const float* wv  = (const float*)d_in[5];
    const float* bv  = (const float*)d_in[6];
    const float* wo  = (const float*)d_in[7];
    const float* bo  = (const float*)d_in[8];
    const float* w1  = (const float*)d_in[9];
    const float* b1  = (const float*)d_in[10];
    const float* w2  = (const float*)d_in[11];
    const float* b2  = (const float*)d_in[12];
    const float* g1  = (const float*)d_in[13];
    const float* be1 = (const float*)d_in[14];
    const float* g2  = (const float*)d_in[15];
    const float* be2 = (const float*)d_in[16];
    float* out = (float*)d_out;

    float *ln1, *q, *k, *vt, *ctx, *h, *ln2, *m1, *sc, *sp, *wt;
    cudaGetSymbolAddress((void**)&ln1, g_ln1);
    cudaGetSymbolAddress((void**)&q,   g_q);
    cudaGetSymbolAddress((void**)&k,   g_k);
    cudaGetSymbolAddress((void**)&vt,  g_vt);
    cudaGetSymbolAddress((void**)&ctx, g_ctx);
    cudaGetSymbolAddress((void**)&h,   g_h);
    cudaGetSymbolAddress((void**)&ln2, g_ln2);
    cudaGetSymbolAddress((void**)&m1,  g_m1);
    cudaGetSymbolAddress((void**)&sc,  g_sc);
    cudaGetSymbolAddress((void**)&sp,  g_sp);
    cudaGetSymbolAddress((void**)&wt,  g_wt);

    float* wqt = wt + 0 * DIM * DIM;
    float* wkt = wt + 1 * DIM * DIM;
    float* wvt = wt + 2 * DIM * DIM;
    float* wot = wt + 3 * DIM * DIM;
    float* w1t = wt + 4 * DIM * DIM;
    float* w2t = wt + 5 * DIM * DIM;

    const int SMEM = 2 * STAGE_BYTES;   // 96KB
    cudaFuncSetAttribute(tf32_gemm<0, false, 0>, cudaFuncAttributeMaxDynamicSharedMemorySize, SMEM);
    cudaFuncSetAttribute(tf32_gemm<0, false, 1>, cudaFuncAttributeMaxDynamicSharedMemorySize, SMEM);
    cudaFuncSetAttribute(tf32_gemm<0, false, 2>, cudaFuncAttributeMaxDynamicSharedMemorySize, SMEM);
    cudaFuncSetAttribute(tf32_gemm<0, true,  1>, cudaFuncAttributeMaxDynamicSharedMemorySize, SMEM);
    cudaFuncSetAttribute(tf32_gemm<1, false, 0>, cudaFuncAttributeMaxDynamicSharedMemorySize, SMEM);
    cudaFuncSetAttribute(tf32_gemm<2, false, 1>, cudaFuncAttributeMaxDynamicSharedMemorySize, SMEM);

    dim3 blk(256);
    dim3 gD(DIM / BN, ROWS / BM, 1);        // dense: (16, 64)
    dim3 gQK(SEQ / BN, SEQ / BM, BATCH);    // (32,16,4)
    dim3 gAV(DIM / BN, SEQ / BM, BATCH);    // (16,16,4)
    dim3 tblk(32, 8);
    dim3 tW(DIM / 32, DIM / 32, 1);

    // LN1 (tf32-rounded)
    ln_kernel<<<ROWS, 256>>>(x, g1, be1, ln1);
    // weight transposes ([K,N] -> [N,K], tf32-rounded)
    transpose_r<<<tW, tblk>>>(wq, wqt, DIM, DIM);
    transpose_r<<<tW, tblk>>>(wk, wkt, DIM, DIM);
    transpose_r<<<tW, tblk>>>(wv, wvt, DIM, DIM);
    transpose_r<<<tW, tblk>>>(wo, wot, DIM, DIM);
    transpose_r<<<tW, tblk>>>(w1, w1t, DIM, DIM);
    transpose_r<<<tW, tblk>>>(w2, w2t, DIM, DIM);
    // Q, K projections (rounded out); V projection writes V^T directly
    tf32_gemm<0, false, 1><<<gD, blk, SMEM>>>(ln1, wqt, bq, nullptr, q,
        DIM, DIM, DIM, DIM, 0, 0, 0);
    tf32_gemm<0, false, 1><<<gD, blk, SMEM>>>(ln1, wkt, bk, nullptr, k,
        DIM, DIM, DIM, DIM, 0, 0, 0);
    tf32_gemm<0, false, 2><<<gD, blk, SMEM>>>(ln1, wvt, bv, nullptr, vt,
        DIM, DIM, DIM, DIM, 0, 0, 0);
    // scores = Q K^T / sqrt(S)  (causal block skip)
    tf32_gemm<1, false, 0><<<gQK, blk, SMEM>>>(q, k, nullptr, nullptr, sc,
        DIM, DIM, DIM, SEQ,
        (size_t)SEQ * DIM, (size_t)SEQ * DIM, (size_t)SEQ * SEQ);
    // softmax -> rounded probs (single-pass)
    softmax_kernel<<<ROWS, 256>>>(sc, sp);
    // ctx = P V  (causal K-limit, heavy-first, rounded out)
    tf32_gemm<2, false, 1><<<gAV, blk, SMEM>>>(sp, vt, nullptr, nullptr, ctx,
        SEQ, SEQ, SEQ, DIM,
        (size_t)SEQ * SEQ, (size_t)SEQ * DIM, (size_t)SEQ * DIM);
    // h = ctx@wo + bo + x
    tf32_gemm<0, false, 0><<<gD, blk, SMEM>>>(ctx, wot, bo, x, h,
        DIM, DIM, DIM, DIM, 0, 0, 0);
    // LN2 (rounded)
    ln_kernel<<<ROWS, 256>>>(h, g2, be2, ln2);
    // mlp1 = relu(ln2@w1 + b1) (rounded out)
    tf32_gemm<0, true, 1><<<gD, blk, SMEM>>>(ln2, w1t, b1, nullptr, m1,
        DIM, DIM, DIM, DIM, 0, 0, 0);
    // out = mlp1@w2 + b2 + h
    tf32_gemm<0, false, 0><<<gD, blk, SMEM>>>(m1, w2t, b2, h, out,
        DIM, DIM, DIM, DIM, 0, 0, 0);
}